// round 8
// baseline (speedup 1.0000x reference)
#include <cuda_runtime.h>
#include <cuda_bf16.h>

// SelfAttention: B=32, D=2048
// q = x@Wq^T+bq ; k,v similarly
// scores[b,i,j] = q_i*k_j ; softmax over i ; out_i = sum_j w_ij * v_j
// Exact column max: m_j = k_j * (k_j>0 ? qmax : qmin)
// Pass1: S_j = sum_i exp(q_i k_j - m_j);  c_j = v_j / S_j
// Pass2: out_i = sum_j c_j * exp(q_i k_j - m_j)
// Passes use dual-pipe exp: half the lanes via MUFU ex2, half via an
// FFMA-pipe exp2 polynomial in packed f32x2 (FFMA2) arithmetic.

#define BB 32
#define DD 2048
#define LOG2E 1.4426950408889634f
#define KSPLIT 4
#define KCHUNK 512            // DD / KSPLIT

typedef unsigned long long ull;

__device__ float g_q[BB * DD];
__device__ float g_k[BB * DD];
__device__ float g_v[BB * DD];
__device__ float g_c[BB * DD];
__device__ float g_part[KSPLIT][3 * BB * DD];   // GEMM partial sums per k-split

__device__ __forceinline__ float ex2f(float x) {
    float r;
    asm("ex2.approx.ftz.f32 %0, %1;" : "=f"(r) : "f"(x));
    return r;
}

// ---- packed f32x2 helpers ----
__device__ __forceinline__ ull fma2(ull a, ull b, ull c) {
    ull d;
    asm("fma.rn.f32x2 %0, %1, %2, %3;" : "=l"(d) : "l"(a), "l"(b), "l"(c));
    return d;
}
__device__ __forceinline__ ull add2(ull a, ull b) {
    ull d;
    asm("add.rn.f32x2 %0, %1, %2;" : "=l"(d) : "l"(a), "l"(b));
    return d;
}
__device__ __forceinline__ ull pack2f(float lo, float hi) {
    ull r;
    asm("mov.b64 %0, {%1, %2};" : "=l"(r) : "f"(lo), "f"(hi));
    return r;
}
__device__ __forceinline__ void unpack2f(ull v, float& lo, float& hi) {
    asm("mov.b64 {%0, %1}, %2;" : "=f"(lo), "=f"(hi) : "l"(v));
}
__device__ __forceinline__ ull pack2u(unsigned int lo, unsigned int hi) {
    ull r;
    asm("mov.b64 %0, {%1, %2};" : "=l"(r) : "r"(lo), "r"(hi));
    return r;
}
__device__ __forceinline__ void unpack2u(ull v, unsigned int& lo, unsigned int& hi) {
    asm("mov.b64 {%0, %1}, %2;" : "=r"(lo), "=r"(hi) : "l"(v));
}

// exp2 poly constants (deg-4 Taylor, |f|<=0.5, rel err <= 6e-5)
#define PC4 0.00961813f
#define PC3 0.05550411f
#define PC2 0.24022651f
#define PC1 0.69314718f
#define MAGICF 12582912.0f            // 1.5 * 2^23
#define ZMINBITS 0x4B3FFF88u          // bits(MAGICF) - 120  (clamp: 2^-120 floor)

// Packed exp2 of one f32x2 pair via FFMA pipe (args must be <= 0).
__device__ __forceinline__ ull exp2_poly2(ull arg, ull MAG2, ull NMAG2, ull MONE2,
                                          ull C4_2, ull C3_2, ull C2_2, ull C1_2, ull ONE2) {
    ull z = add2(arg, MAG2);           // round(arg) in low mantissa bits
    ull t = add2(z, NMAG2);            // t = round(arg) as float
    ull f = fma2(t, MONE2, arg);       // f = arg - t, in [-0.5, 0.5]
    ull p = fma2(C4_2, f, C3_2);
    p = fma2(p, f, C2_2);
    p = fma2(p, f, C1_2);
    p = fma2(p, f, ONE2);              // 2^f
    unsigned int zl, zh, pl, ph;
    unpack2u(z, zl, zh);
    unpack2u(p, pl, ph);
    zl = (unsigned int)max((int)zl, (int)ZMINBITS);
    zh = (unsigned int)max((int)zh, (int)ZMINBITS);
    unsigned int rl = pl + (zl << 23); // insert 2^i exponent
    unsigned int rh = ph + (zh << 23);
    return pack2u(rl, rh);
}

// ---------------------------------------------------------------------------
// Kernel A: q/k/v GEMM partials.
// grid = 384 (= KSPLIT * 3 mats * 32 n-tiles), 128 threads.
// CTA tile: 32m x 64n over a 512-wide K chunk. Thread tile 4m x 4n.
// ---------------------------------------------------------------------------
__global__ void __launch_bounds__(128) qkv_gemm_part(
    const float* __restrict__ x,
    const float* __restrict__ Wq,
    const float* __restrict__ Wk,
    const float* __restrict__ Wv)
{
    const int bx  = blockIdx.x;
    const int ks  = bx / 96;            // k-split index 0..3
    const int r   = bx % 96;
    const int mat = r >> 5;             // 0=q,1=k,2=v
    const int nt  = r & 31;
    const int n0  = nt * 64;
    const int k0  = ks * KCHUNK;

    const float* W = (mat == 0) ? Wq : (mat == 1) ? Wk : Wv;

    __shared__ float xs[2][32][36];     // [buf][kk][m]
    __shared__ float ws[2][32][68];     // [buf][kk][n]

    const int tid = threadIdx.x;
    const int tn  = tid & 15;
    const int tm  = tid >> 4;

    const int xm  = tid >> 2;
    const int xk4 = (tid & 3) * 4;
    const int wn  = tid >> 3;
    const int wk4 = (tid & 7) * 4;

    float acc[4][4];
#pragma unroll
    for (int a = 0; a < 4; a++)
#pragma unroll
        for (int c = 0; c < 4; c++) acc[a][c] = 0.f;

    float4 xr[2], wr[4];

#pragma unroll
    for (int l = 0; l < 2; l++)
        xr[l] = *reinterpret_cast<const float4*>(&x[xm * DD + k0 + xk4 + 16 * l]);
#pragma unroll
    for (int l = 0; l < 4; l++)
        wr[l] = *reinterpret_cast<const float4*>(&W[(n0 + wn + 16 * l) * DD + k0 + wk4]);
#pragma unroll
    for (int l = 0; l < 2; l++) {
        const int kk = xk4 + 16 * l;
        xs[0][kk + 0][xm] = xr[l].x;
        xs[0][kk + 1][xm] = xr[l].y;
        xs[0][kk + 2][xm] = xr[l].z;
        xs[0][kk + 3][xm] = xr[l].w;
    }
#pragma unroll
    for (int l = 0; l < 4; l++) {
        const int n = wn + 16 * l;
        ws[0][wk4 + 0][n] = wr[l].x;
        ws[0][wk4 + 1][n] = wr[l].y;
        ws[0][wk4 + 2][n] = wr[l].z;
        ws[0][wk4 + 3][n] = wr[l].w;
    }

    const int NSTAGE = KCHUNK / 32;     // 16
    for (int kt = 0; kt < NSTAGE; kt++) {
        const int p = kt & 1;
        __syncthreads();

        if (kt < NSTAGE - 1) {
            const int kb = k0 + (kt + 1) * 32;
#pragma unroll
            for (int l = 0; l < 2; l++)
                xr[l] = *reinterpret_cast<const float4*>(&x[xm * DD + kb + xk4 + 16 * l]);
#pragma unroll
            for (int l = 0; l < 4; l++)
                wr[l] = *reinterpret_cast<const float4*>(&W[(n0 + wn + 16 * l) * DD + kb + wk4]);
        }

#pragma unroll
        for (int kk = 0; kk < 32; kk++) {
            const float4 xv = *reinterpret_cast<const float4*>(&xs[p][kk][tm * 4]);
            const float4 wv = *reinterpret_cast<const float4*>(&ws[p][kk][tn * 4]);
            acc[0][0] = fmaf(xv.x, wv.x, acc[0][0]);
            acc[0][1] = fmaf(xv.x, wv.y, acc[0][1]);
            acc[0][2] = fmaf(xv.x, wv.z, acc[0][2]);
            acc[0][3] = fmaf(xv.x, wv.w, acc[0][3]);
            acc[1][0] = fmaf(xv.y, wv.x, acc[1][0]);
            acc[1][1] = fmaf(xv.y, wv.y, acc[1][1]);
            acc[1][2] = fmaf(xv.y, wv.z, acc[1][2]);
            acc[1][3] = fmaf(xv.y, wv.w, acc[1][3]);
            acc[2][0] = fmaf(xv.z, wv.x, acc[2][0]);
            acc[2][1] = fmaf(xv.z, wv.y, acc[2][1]);
            acc[2][2] = fmaf(xv.z, wv.z, acc[2][2]);
            acc[2][3] = fmaf(xv.z, wv.w, acc[2][3]);
            acc[3][0] = fmaf(xv.w, wv.x, acc[3][0]);
            acc[3][1] = fmaf(xv.w, wv.y, acc[3][1]);
            acc[3][2] = fmaf(xv.w, wv.z, acc[3][2]);
            acc[3][3] = fmaf(xv.w, wv.w, acc[3][3]);
        }

        if (kt < NSTAGE - 1) {
            const int np = p ^ 1;
#pragma unroll
            for (int l = 0; l < 2; l++) {
                const int kk = xk4 + 16 * l;
                xs[np][kk + 0][xm] = xr[l].x;
                xs[np][kk + 1][xm] = xr[l].y;
                xs[np][kk + 2][xm] = xr[l].z;
                xs[np][kk + 3][xm] = xr[l].w;
            }
#pragma unroll
            for (int l = 0; l < 4; l++) {
                const int n = wn + 16 * l;
                ws[np][wk4 + 0][n] = wr[l].x;
                ws[np][wk4 + 1][n] = wr[l].y;
                ws[np][wk4 + 2][n] = wr[l].z;
                ws[np][wk4 + 3][n] = wr[l].w;
            }
        }
    }

    float* dst = g_part[ks];
#pragma unroll
    for (int a = 0; a < 4; a++) {
        const int m = tm * 4 + a;
        float4 v = make_float4(acc[a][0], acc[a][1], acc[a][2], acc[a][3]);
        *reinterpret_cast<float4*>(&dst[(mat * BB + m) * DD + n0 + tn * 4]) = v;
    }
}

// ---------------------------------------------------------------------------
// Kernel A2: combine k-split partials + bias -> g_q/g_k/g_v.
// ---------------------------------------------------------------------------
__global__ void __launch_bounds__(512) qkv_combine(
    const float* __restrict__ bq,
    const float* __restrict__ bk,
    const float* __restrict__ bv)
{
    const int idx4 = blockIdx.x * 512 + threadIdx.x;   // 0..49151
    const float4 p0 = reinterpret_cast<const float4*>(g_part[0])[idx4];
    const float4 p1 = reinterpret_cast<const float4*>(g_part[1])[idx4];
    const float4 p2 = reinterpret_cast<const float4*>(g_part[2])[idx4];
    const float4 p3 = reinterpret_cast<const float4*>(g_part[3])[idx4];

    const int mat  = idx4 / (BB * DD / 4);
    const int rem  = idx4 % (BB * DD / 4);
    const int col4 = idx4 % (DD / 4);

    const float* bias = (mat == 0) ? bq : (mat == 1) ? bk : bv;
    const float4 b4 = reinterpret_cast<const float4*>(bias)[col4];

    float4 o;
    o.x = (p0.x + p1.x) + (p2.x + p3.x) + b4.x;
    o.y = (p0.y + p1.y) + (p2.y + p3.y) + b4.y;
    o.z = (p0.z + p1.z) + (p2.z + p3.z) + b4.z;
    o.w = (p0.w + p1.w) + (p2.w + p3.w) + b4.w;

    float* dst = (mat == 0) ? g_q : (mat == 1) ? g_k : g_v;
    reinterpret_cast<float4*>(dst)[rem] = o;
}

// ---------------------------------------------------------------------------
// Block-level max/min reduction helper (512 threads).
// ---------------------------------------------------------------------------
__device__ __forceinline__ void reduce_qmaxmin(
    float lmax, float lmin,
    float* redmax, float* redmin,
    float* s_qmax, float* s_qmin, int tid)
{
#pragma unroll
    for (int o = 16; o; o >>= 1) {
        lmax = fmaxf(lmax, __shfl_xor_sync(0xffffffffu, lmax, o));
        lmin = fminf(lmin, __shfl_xor_sync(0xffffffffu, lmin, o));
    }
    if ((tid & 31) == 0) { redmax[tid >> 5] = lmax; redmin[tid >> 5] = lmin; }
    __syncthreads();
    if (tid < 16) {
        lmax = redmax[tid];
        lmin = redmin[tid];
#pragma unroll
        for (int o = 8; o; o >>= 1) {
            lmax = fmaxf(lmax, __shfl_xor_sync(0xffffu, lmax, o));
            lmin = fminf(lmin, __shfl_xor_sync(0xffffu, lmin, o));
        }
        if (tid == 0) { *s_qmax = lmax; *s_qmin = lmin; }
    }
    __syncthreads();
}

#define DECL_POLY_CONSTS \
    const ull MAG2  = pack2f(MAGICF, MAGICF);   \
    const ull NMAG2 = pack2f(-MAGICF, -MAGICF); \
    const ull MONE2 = pack2f(-1.0f, -1.0f);     \
    const ull C4_2  = pack2f(PC4, PC4);         \
    const ull C3_2  = pack2f(PC3, PC3);         \
    const ull C2_2  = pack2f(PC2, PC2);         \
    const ull C1_2  = pack2f(PC1, PC1);         \
    const ull ONE2  = pack2f(1.0f, 1.0f)

// ---------------------------------------------------------------------------
// Kernel B: pass 1.  grid (4, 32), 512 threads. Thread handles one column j.
// Per 8 i's: 4 via MUFU ex2, 4 via FFMA2 exp2 poly.
// ---------------------------------------------------------------------------
__global__ void __launch_bounds__(512) attn_pass1()
{
    const int b   = blockIdx.y;
    const int tid = threadIdx.x;

    __shared__ ull   qs8[DD / 2];
    __shared__ float redmax[16], redmin[16];
    __shared__ float s_qmax, s_qmin;

    float* qs = reinterpret_cast<float*>(qs8);
    const float* qrow = g_q + b * DD;
    float lmax = -3.402823466e38f, lmin = 3.402823466e38f;
#pragma unroll
    for (int t = tid; t < DD; t += 512) {
        float v = qrow[t];
        qs[t] = v;
        lmax = fmaxf(lmax, v);
        lmin = fminf(lmin, v);
    }
    reduce_qmaxmin(lmax, lmin, redmax, redmin, &s_qmax, &s_qmin, tid);

    const int   j  = blockIdx.x * 512 + tid;
    const float kj = g_k[b * DD + j];
    const float k2 = kj * LOG2E;
    const float nm2 = -(k2 * (kj > 0.f ? s_qmax : s_qmin));

    const ull KK2 = pack2f(k2, k2);
    const ull NN2 = pack2f(nm2, nm2);
    DECL_POLY_CONSTS;

    ull am0 = 0ULL, am1 = 0ULL, ap0 = 0ULL, ap1 = 0ULL;

#pragma unroll 2
    for (int h = 0; h < DD / 2; h += 4) {
        // MUFU lanes (pairs 0,1)
        ull a0 = fma2(qs8[h + 0], KK2, NN2);
        ull a1 = fma2(qs8[h + 1], KK2, NN2);
        float f0, f1, f2, f3;
        unpack2f(a0, f0, f1);
        unpack2f(a1, f2, f3);
        ull e0 = pack2f(ex2f(f0), ex2f(f1));
        ull e1 = pack2f(ex2f(f2), ex2f(f3));
        am0 = add2(am0, e0);
        am1 = add2(am1, e1);
        // Poly lanes (pairs 2,3)
        ull a2 = fma2(qs8[h + 2], KK2, NN2);
        ull a3 = fma2(qs8[h + 3], KK2, NN2);
        ull e2 = exp2_poly2(a2, MAG2, NMAG2, MONE2, C4_2, C3_2, C2_2, C1_2, ONE2);
        ull e3 = exp2_poly2(a3, MAG2, NMAG2, MONE2, C4_2, C3_2, C2_2, C1_2, ONE2);
        ap0 = add2(ap0, e2);
        ap1 = add2(ap1, e3);
    }

    float s0, s1, s2, s3, s4, s5, s6, s7;
    unpack2f(am0, s0, s1);
    unpack2f(am1, s2, s3);
    unpack2f(ap0, s4, s5);
    unpack2f(ap1, s6, s7);
    const float S = ((s0 + s1) + (s2 + s3)) + ((s4 + s5) + (s6 + s7));
    g_c[b * DD + j] = g_v[b * DD + j] / S;
}

// ---------------------------------------------------------------------------
// Kernel C: pass 2.  grid (4, 32), 512 threads. Thread handles one row i.
// SoA smem (k2 / nm2 / c), dual-pipe exp as in pass 1.
// ---------------------------------------------------------------------------
__global__ void __launch_bounds__(512) attn_pass2(float* __restrict__ out)
{
    const int b   = blockIdx.y;
    const int tid = threadIdx.x;

    __shared__ ull   qs8[DD / 2];
    __shared__ ull   sk2[DD / 2];
    __shared__ ull   snm[DD / 2];
    __shared__ ull   sc[DD / 2];
    __shared__ float redmax[16], redmin[16];
    __shared__ float s_qmax, s_qmin;

    float* qs  = reinterpret_cast<float*>(qs8);
    float* k2a = reinterpret_cast<float*>(sk2);
    float* nma = reinterpret_cast<float*>(snm);
    float* ca  = reinterpret_cast<float*>(sc);

    const float* qrow = g_q + b * DD;
    float lmax = -3.402823466e38f, lmin = 3.402823466e38f;
#pragma unroll
    for (int t = tid; t < DD; t += 512) {
        float v = qrow[t];
        qs[t] = v;
        lmax = fmaxf(lmax, v);
        lmin = fminf(lmin, v);
    }
    reduce_qmaxmin(lmax, lmin, redmax, redmin, &s_qmax, &s_qmin, tid);

    const float qmx = s_qmax, qmn = s_qmin;
#pragma unroll
    for (int t = tid; t < DD; t += 512) {
        float kj = g_k[b * DD + t];
        float k2 = kj * LOG2E;
        float nm2 = -(k2 * (kj > 0.f ? qmx : qmn));
        k2a[t] = k2;
        nma[t] = nm2;
        ca[t]  = g_c[b * DD + t];
    }
    __syncthreads();

    const int   i  = blockIdx.x * 512 + tid;
    const float qi = qs[i];
    const ull QQ = pack2f(qi, qi);
    DECL_POLY_CONSTS;

    ull am0 = 0ULL, am1 = 0ULL, ap0 = 0ULL, ap1 = 0ULL;

#pragma unroll 2
    for (int h = 0; h < DD / 2; h += 4) {
        // MUFU lanes (pairs 0,1)
        ull a0 = fma2(QQ, sk2[h + 0], snm[h + 0]);
        ull a1 = fma2(QQ, sk2[h + 1], snm[h + 1]);
        float f0, f1, f2, f3;
        unpack2f(a0, f0, f1);
        unpack2f(a1, f2, f3);
        ull e0 = pack2f(ex2f(f0), ex2f(f1));
        ull e1 = pack2f(ex2f(f2), ex2f(f3));
        am0 = fma2(sc[h + 0], e0, am0);
        am1 = fma2(sc[h + 1], e1, am1);
        // Poly lanes (pairs 2,3)
        ull a2 = fma2(QQ, sk2[h + 2], snm[h + 2]);
        ull a3 = fma2(QQ, sk2[h + 3], snm[h + 3]);
        ull e2 = exp2_poly2(a2, MAG2, NMAG2, MONE2, C4_2, C3_2, C2_2, C1_2, ONE2);
        ull e3 = exp2_poly2(a3, MAG2, NMAG2, MONE2, C4_2, C3_2, C2_2, C1_2, ONE2);
        ap0 = fma2(sc[h + 2], e2, ap0);
        ap1 = fma2(sc[h + 3], e3, ap1);
    }

    float s0, s1, s2, s3, s4, s5, s6, s7;
    unpack2f(am0, s0, s1);
    unpack2f(am1, s2, s3);
    unpack2f(ap0, s4, s5);
    unpack2f(ap1, s6, s7);
    out[b * DD + i] = ((s0 + s1) + (s2 + s3)) + ((s4 + s5) + (s6 + s7));
}

// ---------------------------------------------------------------------------

extern "C" void kernel_launch(void* const* d_in, const int* in_sizes, int n_in,
                              void* d_out, int out_size)
{
    const float* x  = (const float*)d_in[0];
    const float* Wq = (const float*)d_in[1];
    const float* bq = (const float*)d_in[2];
    const float* Wk = (const float*)d_in[3];
    const float* bk = (const float*)d_in[4];
    const float* Wv = (const float*)d_in[5];
    const float* bv = (const float*)d_in[6];
    float* out = (float*)d_out;

    qkv_gemm_part<<<384, 128>>>(x, Wq, Wk, Wv);
    qkv_combine<<<96, 512>>>(bq, bk, bv);
    attn_pass1<<<dim3(4, 32), 512>>>();
    attn_pass2<<<dim3(4, 32), 512>>>(out);
}

// round 11
// speedup vs baseline: 1.1011x; 1.1011x over previous
#include <cuda_runtime.h>
#include <cuda_bf16.h>

// SelfAttention: B=32, D=2048
// q = x@Wq^T+bq ; k,v similarly
// scores[b,i,j] = q_i*k_j ; softmax over i ; out_i = sum_j w_ij * v_j
// Exact column max: m_j = k_j * (k_j>0 ? qmax : qmin)
// Pass1: S_j = sum_i exp(q_i k_j - m_j);  c_j = v_j / S_j
// Pass2: out_i = sum_j c_j * exp(q_i k_j - m_j)
// Passes: dual-pipe exp (5 pairs MUFU : 3 pairs FFMA2-poly per 16 elems),
// reduction dim split in half per thread (512-thr blocks, grid (8,32))
// so critical SMs hold 2 CTAs = 8 warps/SMSP.

#define BB 32
#define DD 2048
#define LOG2E 1.4426950408889634f
#define KSPLIT 4
#define KCHUNK 512            // DD / KSPLIT

typedef unsigned long long ull;

__device__ float g_q[BB * DD];
__device__ float g_k[BB * DD];
__device__ float g_v[BB * DD];
__device__ float g_c[BB * DD];
__device__ float g_part[KSPLIT][3 * BB * DD];   // GEMM partial sums per k-split

__device__ __forceinline__ float ex2f(float x) {
    float r;
    asm("ex2.approx.ftz.f32 %0, %1;" : "=f"(r) : "f"(x));
    return r;
}

// ---- packed f32x2 helpers ----
__device__ __forceinline__ ull fma2(ull a, ull b, ull c) {
    ull d;
    asm("fma.rn.f32x2 %0, %1, %2, %3;" : "=l"(d) : "l"(a), "l"(b), "l"(c));
    return d;
}
__device__ __forceinline__ ull add2(ull a, ull b) {
    ull d;
    asm("add.rn.f32x2 %0, %1, %2;" : "=l"(d) : "l"(a), "l"(b));
    return d;
}
__device__ __forceinline__ ull pack2f(float lo, float hi) {
    ull r;
    asm("mov.b64 %0, {%1, %2};" : "=l"(r) : "f"(lo), "f"(hi));
    return r;
}
__device__ __forceinline__ void unpack2f(ull v, float& lo, float& hi) {
    asm("mov.b64 {%0, %1}, %2;" : "=f"(lo), "=f"(hi) : "l"(v));
}
__device__ __forceinline__ ull pack2u(unsigned int lo, unsigned int hi) {
    ull r;
    asm("mov.b64 %0, {%1, %2};" : "=l"(r) : "r"(lo), "r"(hi));
    return r;
}
__device__ __forceinline__ void unpack2u(ull v, unsigned int& lo, unsigned int& hi) {
    asm("mov.b64 {%0, %1}, %2;" : "=r"(lo), "=r"(hi) : "l"(v));
}

// exp2 poly constants (deg-4 Taylor, |f|<=0.5, rel err <= 6e-5)
#define PC4 0.00961813f
#define PC3 0.05550411f
#define PC2 0.24022651f
#define PC1 0.69314718f
#define MAGICF 12582912.0f            // 1.5 * 2^23
#define ZMINBITS 0x4B3FFF88u          // bits(MAGICF) - 120  (clamp: 2^-120 floor)

// Packed exp2 of one f32x2 pair via FFMA pipe (args must be <= 0).
__device__ __forceinline__ ull exp2_poly2(ull arg, ull MAG2, ull NMAG2, ull MONE2,
                                          ull C4_2, ull C3_2, ull C2_2, ull C1_2, ull ONE2) {
    ull z = add2(arg, MAG2);           // round(arg) in low mantissa bits
    ull t = add2(z, NMAG2);            // t = round(arg) as float
    ull f = fma2(t, MONE2, arg);       // f = arg - t, in [-0.5, 0.5]
    ull p = fma2(C4_2, f, C3_2);
    p = fma2(p, f, C2_2);
    p = fma2(p, f, C1_2);
    p = fma2(p, f, ONE2);              // 2^f
    unsigned int zl, zh, pl, ph;
    unpack2u(z, zl, zh);
    unpack2u(p, pl, ph);
    zl = (unsigned int)max((int)zl, (int)ZMINBITS);
    zh = (unsigned int)max((int)zh, (int)ZMINBITS);
    unsigned int rl = pl + (zl << 23); // insert 2^i exponent
    unsigned int rh = ph + (zh << 23);
    return pack2u(rl, rh);
}

#define DECL_POLY_CONSTS \
    const ull MAG2  = pack2f(MAGICF, MAGICF);   \
    const ull NMAG2 = pack2f(-MAGICF, -MAGICF); \
    const ull MONE2 = pack2f(-1.0f, -1.0f);     \
    const ull C4_2  = pack2f(PC4, PC4);         \
    const ull C3_2  = pack2f(PC3, PC3);         \
    const ull C2_2  = pack2f(PC2, PC2);         \
    const ull C1_2  = pack2f(PC1, PC1);         \
    const ull ONE2  = pack2f(1.0f, 1.0f)

// ---------------------------------------------------------------------------
// Kernel A: q/k/v GEMM partials. (unchanged)
// ---------------------------------------------------------------------------
__global__ void __launch_bounds__(128) qkv_gemm_part(
    const float* __restrict__ x,
    const float* __restrict__ Wq,
    const float* __restrict__ Wk,
    const float* __restrict__ Wv)
{
    const int bx  = blockIdx.x;
    const int ks  = bx / 96;
    const int r   = bx % 96;
    const int mat = r >> 5;
    const int nt  = r & 31;
    const int n0  = nt * 64;
    const int k0  = ks * KCHUNK;

    const float* W = (mat == 0) ? Wq : (mat == 1) ? Wk : Wv;

    __shared__ float xs[2][32][36];
    __shared__ float ws[2][32][68];

    const int tid = threadIdx.x;
    const int tn  = tid & 15;
    const int tm  = tid >> 4;

    const int xm  = tid >> 2;
    const int xk4 = (tid & 3) * 4;
    const int wn  = tid >> 3;
    const int wk4 = (tid & 7) * 4;

    float acc[4][4];
#pragma unroll
    for (int a = 0; a < 4; a++)
#pragma unroll
        for (int c = 0; c < 4; c++) acc[a][c] = 0.f;

    float4 xr[2], wr[4];

#pragma unroll
    for (int l = 0; l < 2; l++)
        xr[l] = *reinterpret_cast<const float4*>(&x[xm * DD + k0 + xk4 + 16 * l]);
#pragma unroll
    for (int l = 0; l < 4; l++)
        wr[l] = *reinterpret_cast<const float4*>(&W[(n0 + wn + 16 * l) * DD + k0 + wk4]);
#pragma unroll
    for (int l = 0; l < 2; l++) {
        const int kk = xk4 + 16 * l;
        xs[0][kk + 0][xm] = xr[l].x;
        xs[0][kk + 1][xm] = xr[l].y;
        xs[0][kk + 2][xm] = xr[l].z;
        xs[0][kk + 3][xm] = xr[l].w;
    }
#pragma unroll
    for (int l = 0; l < 4; l++) {
        const int n = wn + 16 * l;
        ws[0][wk4 + 0][n] = wr[l].x;
        ws[0][wk4 + 1][n] = wr[l].y;
        ws[0][wk4 + 2][n] = wr[l].z;
        ws[0][wk4 + 3][n] = wr[l].w;
    }

    const int NSTAGE = KCHUNK / 32;
    for (int kt = 0; kt < NSTAGE; kt++) {
        const int p = kt & 1;
        __syncthreads();

        if (kt < NSTAGE - 1) {
            const int kb = k0 + (kt + 1) * 32;
#pragma unroll
            for (int l = 0; l < 2; l++)
                xr[l] = *reinterpret_cast<const float4*>(&x[xm * DD + kb + xk4 + 16 * l]);
#pragma unroll
            for (int l = 0; l < 4; l++)
                wr[l] = *reinterpret_cast<const float4*>(&W[(n0 + wn + 16 * l) * DD + kb + wk4]);
        }

#pragma unroll
        for (int kk = 0; kk < 32; kk++) {
            const float4 xv = *reinterpret_cast<const float4*>(&xs[p][kk][tm * 4]);
            const float4 wv = *reinterpret_cast<const float4*>(&ws[p][kk][tn * 4]);
            acc[0][0] = fmaf(xv.x, wv.x, acc[0][0]);
            acc[0][1] = fmaf(xv.x, wv.y, acc[0][1]);
            acc[0][2] = fmaf(xv.x, wv.z, acc[0][2]);
            acc[0][3] = fmaf(xv.x, wv.w, acc[0][3]);
            acc[1][0] = fmaf(xv.y, wv.x, acc[1][0]);
            acc[1][1] = fmaf(xv.y, wv.y, acc[1][1]);
            acc[1][2] = fmaf(xv.y, wv.z, acc[1][2]);
            acc[1][3] = fmaf(xv.y, wv.w, acc[1][3]);
            acc[2][0] = fmaf(xv.z, wv.x, acc[2][0]);
            acc[2][1] = fmaf(xv.z, wv.y, acc[2][1]);
            acc[2][2] = fmaf(xv.z, wv.z, acc[2][2]);
            acc[2][3] = fmaf(xv.z, wv.w, acc[2][3]);
            acc[3][0] = fmaf(xv.w, wv.x, acc[3][0]);
            acc[3][1] = fmaf(xv.w, wv.y, acc[3][1]);
            acc[3][2] = fmaf(xv.w, wv.z, acc[3][2]);
            acc[3][3] = fmaf(xv.w, wv.w, acc[3][3]);
        }

        if (kt < NSTAGE - 1) {
            const int np = p ^ 1;
#pragma unroll
            for (int l = 0; l < 2; l++) {
                const int kk = xk4 + 16 * l;
                xs[np][kk + 0][xm] = xr[l].x;
                xs[np][kk + 1][xm] = xr[l].y;
                xs[np][kk + 2][xm] = xr[l].z;
                xs[np][kk + 3][xm] = xr[l].w;
            }
#pragma unroll
            for (int l = 0; l < 4; l++) {
                const int n = wn + 16 * l;
                ws[np][wk4 + 0][n] = wr[l].x;
                ws[np][wk4 + 1][n] = wr[l].y;
                ws[np][wk4 + 2][n] = wr[l].z;
                ws[np][wk4 + 3][n] = wr[l].w;
            }
        }
    }

    float* dst = g_part[ks];
#pragma unroll
    for (int a = 0; a < 4; a++) {
        const int m = tm * 4 + a;
        float4 v = make_float4(acc[a][0], acc[a][1], acc[a][2], acc[a][3]);
        *reinterpret_cast<float4*>(&dst[(mat * BB + m) * DD + n0 + tn * 4]) = v;
    }
}

// ---------------------------------------------------------------------------
// Kernel A2: combine k-split partials + bias -> g_q/g_k/g_v. (unchanged)
// ---------------------------------------------------------------------------
__global__ void __launch_bounds__(512) qkv_combine(
    const float* __restrict__ bq,
    const float* __restrict__ bk,
    const float* __restrict__ bv)
{
    const int idx4 = blockIdx.x * 512 + threadIdx.x;
    const float4 p0 = reinterpret_cast<const float4*>(g_part[0])[idx4];
    const float4 p1 = reinterpret_cast<const float4*>(g_part[1])[idx4];
    const float4 p2 = reinterpret_cast<const float4*>(g_part[2])[idx4];
    const float4 p3 = reinterpret_cast<const float4*>(g_part[3])[idx4];

    const int mat  = idx4 / (BB * DD / 4);
    const int rem  = idx4 % (BB * DD / 4);
    const int col4 = idx4 % (DD / 4);

    const float* bias = (mat == 0) ? bq : (mat == 1) ? bk : bv;
    const float4 b4 = reinterpret_cast<const float4*>(bias)[col4];

    float4 o;
    o.x = (p0.x + p1.x) + (p2.x + p3.x) + b4.x;
    o.y = (p0.y + p1.y) + (p2.y + p3.y) + b4.y;
    o.z = (p0.z + p1.z) + (p2.z + p3.z) + b4.z;
    o.w = (p0.w + p1.w) + (p2.w + p3.w) + b4.w;

    float* dst = (mat == 0) ? g_q : (mat == 1) ? g_k : g_v;
    reinterpret_cast<float4*>(dst)[rem] = o;
}

// ---------------------------------------------------------------------------
// Block-level max/min reduction helper (512 threads).
// ---------------------------------------------------------------------------
__device__ __forceinline__ void reduce_qmaxmin(
    float lmax, float lmin,
    float* redmax, float* redmin,
    float* s_qmax, float* s_qmin, int tid)
{
#pragma unroll
    for (int o = 16; o; o >>= 1) {
        lmax = fmaxf(lmax, __shfl_xor_sync(0xffffffffu, lmax, o));
        lmin = fminf(lmin, __shfl_xor_sync(0xffffffffu, lmin, o));
    }
    if ((tid & 31) == 0) { redmax[tid >> 5] = lmax; redmin[tid >> 5] = lmin; }
    __syncthreads();
    if (tid < 16) {
        lmax = redmax[tid];
        lmin = redmin[tid];
#pragma unroll
        for (int o = 8; o; o >>= 1) {
            lmax = fmaxf(lmax, __shfl_xor_sync(0xffffu, lmax, o));
            lmin = fminf(lmin, __shfl_xor_sync(0xffffu, lmin, o));
        }
        if (tid == 0) { *s_qmax = lmax; *s_qmin = lmin; }
    }
    __syncthreads();
}

// Dual-pipe body macro: 8 ull (16 elems) from array ARR at [base+h+*]:
// pairs 0..4 via MUFU, pairs 5..7 via FFMA2 poly.
// ARG(idx) must produce the packed exp2 argument for ull index (base+h+idx).
// ACCM(n, e) / ACCP(n, e) fold exp results into accumulators.

// ---------------------------------------------------------------------------
// Kernel B: pass 1.  grid (8, 32), 512 threads.
// j = bx*256 + (tid&255); half = tid>>8 owns i-range [half*1024, +1024).
// ---------------------------------------------------------------------------
__global__ void __launch_bounds__(512) attn_pass1()
{
    const int b   = blockIdx.y;
    const int bx  = blockIdx.x;
    const int tid = threadIdx.x;

    __shared__ ull   qs8[DD / 2];      // 8 KB
    __shared__ float Sh[512];          // 2 KB
    __shared__ float redmax[16], redmin[16];
    __shared__ float s_qmax, s_qmin;

    float* qs = reinterpret_cast<float*>(qs8);
    const float* qrow = g_q + b * DD;
    float lmax = -3.402823466e38f, lmin = 3.402823466e38f;
#pragma unroll
    for (int t = tid; t < DD; t += 512) {
        float v = qrow[t];
        qs[t] = v;
        lmax = fmaxf(lmax, v);
        lmin = fminf(lmin, v);
    }
    reduce_qmaxmin(lmax, lmin, redmax, redmin, &s_qmax, &s_qmin, tid);

    const int   j    = bx * 256 + (tid & 255);
    const int   base = (tid >> 8) * (DD / 4);   // 0 or 512 (ull index)
    const float kj = g_k[b * DD + j];
    const float k2 = kj * LOG2E;
    const float nm2 = -(k2 * (kj > 0.f ? s_qmax : s_qmin));

    const ull KK2 = pack2f(k2, k2);
    const ull NN2 = pack2f(nm2, nm2);
    DECL_POLY_CONSTS;

    ull am0 = 0ULL, am1 = 0ULL, am2 = 0ULL, am3 = 0ULL, am4 = 0ULL;
    ull ap0 = 0ULL, ap1 = 0ULL, ap2 = 0ULL;

    for (int h = 0; h < DD / 4; h += 8) {
        const ull* qp = &qs8[base + h];
        // MUFU pairs 0..4
        ull a0 = fma2(qp[0], KK2, NN2);
        ull a1 = fma2(qp[1], KK2, NN2);
        ull a2 = fma2(qp[2], KK2, NN2);
        ull a3 = fma2(qp[3], KK2, NN2);
        ull a4 = fma2(qp[4], KK2, NN2);
        float f0, f1, f2, f3, f4, f5, f6, f7, f8, f9;
        unpack2f(a0, f0, f1);
        unpack2f(a1, f2, f3);
        unpack2f(a2, f4, f5);
        unpack2f(a3, f6, f7);
        unpack2f(a4, f8, f9);
        am0 = add2(am0, pack2f(ex2f(f0), ex2f(f1)));
        am1 = add2(am1, pack2f(ex2f(f2), ex2f(f3)));
        am2 = add2(am2, pack2f(ex2f(f4), ex2f(f5)));
        am3 = add2(am3, pack2f(ex2f(f6), ex2f(f7)));
        am4 = add2(am4, pack2f(ex2f(f8), ex2f(f9)));
        // Poly pairs 5..7
        ull a5 = fma2(qp[5], KK2, NN2);
        ull a6 = fma2(qp[6], KK2, NN2);
        ull a7 = fma2(qp[7], KK2, NN2);
        ap0 = add2(ap0, exp2_poly2(a5, MAG2, NMAG2, MONE2, C4_2, C3_2, C2_2, C1_2, ONE2));
        ap1 = add2(ap1, exp2_poly2(a6, MAG2, NMAG2, MONE2, C4_2, C3_2, C2_2, C1_2, ONE2));
        ap2 = add2(ap2, exp2_poly2(a7, MAG2, NMAG2, MONE2, C4_2, C3_2, C2_2, C1_2, ONE2));
    }

    ull t0 = add2(add2(am0, am1), add2(am2, am3));
    ull t1 = add2(am4, add2(ap0, add2(ap1, ap2)));
    ull tt = add2(t0, t1);
    float slo, shi;
    unpack2f(tt, slo, shi);
    Sh[tid] = slo + shi;
    __syncthreads();
    if (tid < 256) {
        const float S = Sh[tid] + Sh[tid + 256];
        g_c[b * DD + j] = g_v[b * DD + j] / S;
    }
}

// ---------------------------------------------------------------------------
// Kernel C: pass 2.  grid (8, 32), 512 threads.
// i = bx*256 + (tid&255); half = tid>>8 owns j-range [half*1024, +1024).
// ---------------------------------------------------------------------------
__global__ void __launch_bounds__(512) attn_pass2(float* __restrict__ out)
{
    const int b   = blockIdx.y;
    const int bx  = blockIdx.x;
    const int tid = threadIdx.x;

    __shared__ ull   qs8[DD / 2];      // 8 KB
    __shared__ ull   sk2[DD / 2];      // 8 KB
    __shared__ ull   snm[DD / 2];      // 8 KB
    __shared__ ull   sc[DD / 2];       // 8 KB
    __shared__ float Sh[512];          // 2 KB
    __shared__ float redmax[16], redmin[16];
    __shared__ float s_qmax, s_qmin;

    float* qs  = reinterpret_cast<float*>(qs8);
    float* k2a = reinterpret_cast<float*>(sk2);
    float* nma = reinterpret_cast<float*>(snm);
    float* ca  = reinterpret_cast<float*>(sc);

    const float* qrow = g_q + b * DD;
    float lmax = -3.402823466e38f, lmin = 3.402823466e38f;
#pragma unroll
    for (int t = tid; t < DD; t += 512) {
        float v = qrow[t];
        qs[t] = v;
        lmax = fmaxf(lmax, v);
        lmin = fminf(lmin, v);
    }
    reduce_qmaxmin(lmax, lmin, redmax, redmin, &s_qmax, &s_qmin, tid);

    const float qmx = s_qmax, qmn = s_qmin;
#pragma unroll
    for (int t = tid; t < DD; t += 512) {
        float kj = g_k[b * DD + t];
        float k2 = kj * LOG2E;
        float nm2 = -(k2 * (kj > 0.f ? qmx : qmn));
        k2a[t] = k2;
        nma[t] = nm2;
        ca[t]  = g_c[b * DD + t];
    }
    __syncthreads();

    const int   i    = bx * 256 + (tid & 255);
    const int   base = (tid >> 8) * (DD / 4);   // 0 or 512 (ull index)
    const float qi = qs[i];
    const ull QQ = pack2f(qi, qi);
    DECL_POLY_CONSTS;

    ull am0 = 0ULL, am1 = 0ULL, am2 = 0ULL, am3 = 0ULL, am4 = 0ULL;
    ull ap0 = 0ULL, ap1 = 0ULL, ap2 = 0ULL;

    for (int h = 0; h < DD / 4; h += 8) {
        const ull* kp = &sk2[base + h];
        const ull* np = &snm[base + h];
        const ull* cp = &sc[base + h];
        // MUFU pairs 0..4
        ull a0 = fma2(QQ, kp[0], np[0]);
        ull a1 = fma2(QQ, kp[1], np[1]);
        ull a2 = fma2(QQ, kp[2], np[2]);
        ull a3 = fma2(QQ, kp[3], np[3]);
        ull a4 = fma2(QQ, kp[4], np[4]);
        float f0, f1, f2, f3, f4, f5, f6, f7, f8, f9;
        unpack2f(a0, f0, f1);
        unpack2f(a1, f2, f3);
        unpack2f(a2, f4, f5);
        unpack2f(a3, f6, f7);
        unpack2f(a4, f8, f9);
        am0 = fma2(cp[0], pack2f(ex2f(f0), ex2f(f1)), am0);
        am1 = fma2(cp[1], pack2f(ex2f(f2), ex2f(f3)), am1);
        am2 = fma2(cp[2], pack2f(ex2f(f4), ex2f(f5)), am2);
        am3 = fma2(cp[3], pack2f(ex2f(f6), ex2f(f7)), am3);
        am4 = fma2(cp[4], pack2f(ex2f(f8), ex2f(f9)), am4);
        // Poly pairs 5..7
        ull a5 = fma2(QQ, kp[5], np[5]);
        ull a6 = fma2(QQ, kp[6], np[6]);
        ull a7 = fma2(QQ, kp[7], np[7]);
        ap0 = fma2(cp[5], exp2_poly2(a5, MAG2, NMAG2, MONE2, C4_2, C3_2, C2_2, C1_2, ONE2), ap0);
        ap1 = fma2(cp[6], exp2_poly2(a6, MAG2, NMAG2, MONE2, C4_2, C3_2, C2_2, C1_2, ONE2), ap1);
        ap2 = fma2(cp[7], exp2_poly2(a7, MAG2, NMAG2, MONE2, C4_2, C3_2, C2_2, C1_2, ONE2), ap2);
    }

    ull t0 = add2(add2(am0, am1), add2(am2, am3));
    ull t1 = add2(am4, add2(ap0, add2(ap1, ap2)));
    ull tt = add2(t0, t1);
    float slo, shi;
    unpack2f(tt, slo, shi);
    Sh[tid] = slo + shi;
    __syncthreads();
    if (tid < 256) {
        out[b * DD + i] = Sh[tid] + Sh[tid + 256];
    }
}

// ---------------------------------------------------------------------------

extern "C" void kernel_launch(void* const* d_in, const int* in_sizes, int n_in,
                              void* d_out, int out_size)
{
    const float* x  = (const float*)d_in[0];
    const float* Wq = (const float*)d_in[1];
    const float* bq = (const float*)d_in[2];
    const float* Wk = (const float*)d_in[3];
    const float* bk = (const float*)d_in[4];
    const float* Wv = (const float*)d_in[5];
    const float* bv = (const float*)d_in[6];
    float* out = (float*)d_out;

    qkv_gemm_part<<<384, 128>>>(x, Wq, Wk, Wv);
    qkv_combine<<<96, 512>>>(bq, bk, bv);
    attn_pass1<<<dim3(8, 32), 512>>>();
    attn_pass2<<<dim3(8, 32), 512>>>(out);
}